// round 7
// baseline (speedup 1.0000x reference)
#include <cuda_runtime.h>
#include <cstdint>

// OMul: r[i] = outer(x[i], y[i]) flattened.
// x: [N, 256] f32, y: [N, 256] f32, out: [N, 65536] f32. 1 GiB of stores.
//
// R7: TMA bulk-store variant. One CTA per row (champion grid shape).
// Compute 8KB chunks (8 m-rows x 256 k) into smem, double-buffered, and
// stream them to GMEM via cp.async.bulk.global.shared::cta — the TMA engine
// presents DRAM with perfect 8KB sequential bursts, removing per-warp STG
// wavefront scheduling from the store path entirely.

static constexpr int M = 256;
static constexpr int K = 256;
static constexpr int THREADS = 256;
static constexpr int CHUNK_M = 8;                    // m-rows per chunk
static constexpr int CHUNK_FLOATS = CHUNK_M * K;     // 2048 floats = 8KB
static constexpr int CHUNK_BYTES = CHUNK_FLOATS * 4; // 8192
static constexpr int NCHUNK = M / CHUNK_M;           // 32

__global__ __launch_bounds__(THREADS, 8)
void omul_kernel(const float* __restrict__ x,
                 const float* __restrict__ y,
                 float* __restrict__ out)
{
    __shared__ float sx[M];
    __shared__ float sy[K];
    __shared__ __align__(128) float sbuf[2][CHUNK_FLOATS];   // 2 x 8KB

    const int row = blockIdx.x;
    const int t   = threadIdx.x;

    sx[t] = x[(size_t)row * M + t];
    sy[t] = y[(size_t)row * K + t];
    __syncthreads();

    const int k4 = t & 63;        // float4 chunk of k (0..63)
    const int m0 = t >> 6;        // 0..3

    const float4 y4 = reinterpret_cast<const float4*>(sy)[k4];

    float* orow = out + (size_t)row * (M * K);

    #pragma unroll 1
    for (int c = 0; c < NCHUNK; c++) {
        // Ensure the buffer we're about to overwrite has been drained by TMA.
        if (c >= 2) {
            if (t == 0) {
                asm volatile("cp.async.bulk.wait_group.read 1;" ::: "memory");
            }
            __syncthreads();
        }

        float4* buf4 = reinterpret_cast<float4*>(sbuf[c & 1]);
        const int m_base = c * CHUNK_M;

        #pragma unroll
        for (int mi = 0; mi < CHUNK_M / 4; mi++) {
            const int ml = m0 + mi * 4;             // 0..7 local m
            const float xv = sx[m_base + ml];       // warp-uniform broadcast
            float4 v;
            v.x = xv * y4.x;
            v.y = xv * y4.y;
            v.z = xv * y4.z;
            v.w = xv * y4.w;
            buf4[ml * 64 + k4] = v;
        }

        // Make generic-proxy smem stores visible to the async proxy.
        asm volatile("fence.proxy.async.shared::cta;" ::: "memory");
        __syncthreads();

        if (t == 0) {
            uint32_t src = (uint32_t)__cvta_generic_to_shared(sbuf[c & 1]);
            float* dst = orow + (size_t)m_base * K;
            asm volatile(
                "cp.async.bulk.global.shared::cta.bulk_group [%0], [%1], %2;"
                :: "l"(dst), "r"(src), "r"(CHUNK_BYTES)
                : "memory");
            asm volatile("cp.async.bulk.commit_group;" ::: "memory");
        }
    }

    // Drain all outstanding bulk stores before exit.
    if (t == 0) {
        asm volatile("cp.async.bulk.wait_group 0;" ::: "memory");
    }
}

extern "C" void kernel_launch(void* const* d_in, const int* in_sizes, int n_in,
                              void* d_out, int out_size)
{
    const float* x = (const float*)d_in[0];
    const float* y = (const float*)d_in[1];
    float* out = (float*)d_out;

    const int n = in_sizes[0] / M;   // 4096 rows

    omul_kernel<<<n, THREADS>>>(x, y, out);
}